// round 11
// baseline (speedup 1.0000x reference)
#include <cuda_runtime.h>
#include <cuda_fp16.h>
#include <cstdint>

// Sinkhorn (eps=0.1, 50 iters) on N=8, P1=P2=2048.
// Exp-domain matrix scaling, fp16 K = exp(-C/eps) (67 MB, L2-resident).
//   a = (mu+1e-8)/(K b);  b = (nu+1e-8)/(K^T a)
// R8: 8-row tiles (32KB smem -> ~6 CTAs/SM, 48 warps/SM) + half2 datapath
// (HMUL2/HADD2 tree in phase A, HFMA2 accum in phase B). a broadcast scaled
// by 4096 (exact) to avoid fp16 denormals on iter 1; fix un-scales.
// K read once/iter; fp16 column partials; deterministic fix kernel.

#define NB 8
#define PP 2048
#define M_ELEMS (NB * (size_t)PP * (size_t)PP)   // 33,554,432
#define INV_EPS 10.0f
#define NITER 50
#define LOGEPS 1e-8f
#define ROWS_PER_CTA 8
#define CBS 256                                   // tiles (partial slices) per batch
#define TILE_BYTES (ROWS_PER_CTA * PP * 2)        // 32768
#define ASCALE 4096.0f

__device__ __half g_K[M_ELEMS];                   // 64 MiB
__device__ float  g_a[NB * PP];
__device__ float  g_b[NB * PP];
__device__ __half g_b_h[NB * PP];
__device__ __half g_tpart[NB * CBS * PP];         // 8 MiB fp16 partials (scaled x4096)
__device__ float  g_part[4096];

// ---------------- small PTX helpers ----------------
__device__ __forceinline__ uint32_t smem_u32(const void* p) {
    uint32_t a;
    asm("{ .reg .u64 t; cvta.to.shared.u64 t, %1; cvt.u32.u64 %0, t; }" : "=r"(a) : "l"(p));
    return a;
}
__device__ __forceinline__ void mbar_init(uint32_t mbar, uint32_t cnt) {
    asm volatile("mbarrier.init.shared.b64 [%0], %1;" :: "r"(mbar), "r"(cnt) : "memory");
}
__device__ __forceinline__ void mbar_expect_tx(uint32_t mbar, uint32_t bytes) {
    asm volatile("mbarrier.arrive.expect_tx.shared.b64 _, [%0], %1;" :: "r"(mbar), "r"(bytes) : "memory");
}
__device__ __forceinline__ void bulk_g2s(uint32_t dst, const void* src, uint32_t bytes, uint32_t mbar) {
    asm volatile("cp.async.bulk.shared::cta.global.mbarrier::complete_tx::bytes [%0], [%1], %2, [%3];"
                 :: "r"(dst), "l"(src), "r"(bytes), "r"(mbar) : "memory");
}
__device__ __forceinline__ void mbar_wait(uint32_t mbar, uint32_t parity) {
    uint32_t done;
    asm volatile("{\n\t.reg .pred p;\n\t"
                 "mbarrier.try_wait.parity.acquire.cta.shared::cta.b64 p, [%1], %2;\n\t"
                 "selp.b32 %0, 1, 0, p;\n\t}"
                 : "=r"(done) : "r"(mbar), "r"(parity) : "memory");
    if (!done) {
        asm volatile("{\n\t.reg .pred P1;\n\t"
                     "WL_%=:\n\t"
                     "mbarrier.try_wait.parity.acquire.cta.shared::cta.b64 P1, [%0], %1, 0x989680;\n\t"
                     "@P1 bra.uni WD_%=;\n\t"
                     "bra.uni WL_%=;\n\t"
                     "WD_%=:\n\t}"
                     :: "r"(mbar), "r"(parity) : "memory");
    }
}

// ---------------------------------------------------------------------------
// Prologue: K = fp16(exp(-C/eps)); init b = 1 (float and half).
// ---------------------------------------------------------------------------
__global__ void __launch_bounds__(256) prologue_kernel(const float* __restrict__ C) {
    size_t tid  = (size_t)blockIdx.x * 256 + threadIdx.x;
    size_t base = tid * 8;
    float4 c0 = *(const float4*)(C + base);
    float4 c1 = *(const float4*)(C + base + 4);
    union { __half2 h2[4]; uint4 u; } pk;
    pk.h2[0] = __floats2half2_rn(__expf(-INV_EPS * c0.x), __expf(-INV_EPS * c0.y));
    pk.h2[1] = __floats2half2_rn(__expf(-INV_EPS * c0.z), __expf(-INV_EPS * c0.w));
    pk.h2[2] = __floats2half2_rn(__expf(-INV_EPS * c1.x), __expf(-INV_EPS * c1.y));
    pk.h2[3] = __floats2half2_rn(__expf(-INV_EPS * c1.z), __expf(-INV_EPS * c1.w));
    *(uint4*)(g_K + base) = pk.u;
    if (tid < (size_t)NB * PP) {
        g_b[tid]   = 1.0f;
        g_b_h[tid] = __float2half(1.0f);
    }
}

// ---------------------------------------------------------------------------
// Fused iteration kernel. grid = 8*256 = 2048 CTAs x 256 threads (8 warps).
// CTA (batch, cb): rows cb*8 .. cb*8+7 (32 KB tile, 2 x 16 KB bulk copies).
//   Phase A: warp w owns row w; lane sums 64 cols via HMUL2/HADD2 tree.
//            a[r] = (mu[r]+1e-8)/s[r]; broadcast (a*4096) as half2.
//   Phase B: thread t owns cols 8t..8t+7; acc_h2 += HFMA2 over 8 rows;
//            store fp16 partials (scaled) to g_tpart[batch][cb][:].
// ---------------------------------------------------------------------------
__global__ void __launch_bounds__(256) iter_kernel(const float* __restrict__ mu) {
    extern __shared__ char smem_raw[];
    __half*   Kt    = (__half*)smem_raw;                        // 32768 B
    __half*   b_sm  = (__half*)(smem_raw + TILE_BYTES);         // 4096 B
    __half2*  a_sm  = (__half2*)(smem_raw + TILE_BYTES + 4096); // 8 half2 = 32 B
    uint64_t* mbar_p = (uint64_t*)(smem_raw + TILE_BYTES + 4096 + 32); // 2 mbars

    int batch = blockIdx.x >> 8;
    int cb    = blockIdx.x & 255;
    int row0  = cb * ROWS_PER_CTA;
    int t = threadIdx.x;
    int w = t >> 5, l = t & 31;

    uint32_t mbar0 = smem_u32(mbar_p);
    uint32_t ktad  = smem_u32(Kt);

    if (t == 0) { mbar_init(mbar0, 1); mbar_init(mbar0 + 8, 1); }
    __syncthreads();
    if (t == 0) {
        asm volatile("fence.proxy.async.shared::cta;" ::: "memory");
        const __half* src = g_K + ((size_t)(batch * PP + row0)) * PP;
        mbar_expect_tx(mbar0, TILE_BYTES / 2);
        bulk_g2s(ktad, src, TILE_BYTES / 2, mbar0);
        mbar_expect_tx(mbar0 + 8, TILE_BYTES / 2);
        bulk_g2s(ktad + TILE_BYTES / 2, src + PP * (ROWS_PER_CTA / 2), TILE_BYTES / 2, mbar0 + 8);
    }

    // Cooperative load of b (fp16) into smem: thread t -> 8 halves at t*8.
    {
        const __half* bp = g_b_h + batch * PP + t * 8;
        *(uint4*)(b_sm + t * 8) = *(const uint4*)bp;
    }
    __syncthreads();

    // Warps 0-3 consume rows 0-3 (chunk 0), warps 4-7 rows 4-7 (chunk 1).
    mbar_wait(mbar0 + (w >= 4 ? 8 : 0), 0);

    // ---- Phase A: warp w sums row w over its lane's 64 columns ----
    {
        const __half* Krow = Kt + w * PP;
        float ax = 0.f, ay = 0.f;
#pragma unroll
        for (int it = 0; it < 8; it++) {
            int off = (it * 32 + l) * 8;
            uint4 kv = *(const uint4*)(Krow + off);
            uint4 bv = *(const uint4*)(b_sm + off);
            const __half2* kh = (const __half2*)&kv;
            const __half2* bh = (const __half2*)&bv;
            __half2 p0 = __hmul2(kh[0], bh[0]);
            __half2 p1 = __hmul2(kh[1], bh[1]);
            __half2 p2 = __hmul2(kh[2], bh[2]);
            __half2 p3 = __hmul2(kh[3], bh[3]);
            __half2 s2 = __hadd2(__hadd2(p0, p1), __hadd2(p2, p3));
            float2 f = __half22float2(s2);
            ax += f.x; ay += f.y;
        }
        float s = ax + ay;
#pragma unroll
        for (int off = 16; off; off >>= 1) s += __shfl_xor_sync(0xffffffffu, s, off);
        if (l == 0) {
            int row = batch * PP + row0 + w;
            float av = (mu[row] + LOGEPS) / s;
            g_a[row] = av;
            a_sm[w]  = __float2half2_rn(av * ASCALE);
        }
    }
    __syncthreads();

    // ---- Phase B: thread t owns cols 8t..8t+7; HFMA2 accum over 8 rows ----
    {
        __half2 acc0 = __float2half2_rn(0.f);
        __half2 acc1 = acc0, acc2 = acc0, acc3 = acc0;
#pragma unroll
        for (int r = 0; r < ROWS_PER_CTA; r++) {
            uint4 kv = *(const uint4*)(Kt + r * PP + t * 8);
            __half2 a2 = a_sm[r];
            const __half2* kh = (const __half2*)&kv;
            acc0 = __hfma2(kh[0], a2, acc0);
            acc1 = __hfma2(kh[1], a2, acc1);
            acc2 = __hfma2(kh[2], a2, acc2);
            acc3 = __hfma2(kh[3], a2, acc3);
        }
        union { __half2 h2[4]; uint4 u; } st;
        st.h2[0] = acc0; st.h2[1] = acc1; st.h2[2] = acc2; st.h2[3] = acc3;
        *(uint4*)(g_tpart + ((size_t)(batch * CBS + cb)) * PP + t * 8) = st.u;
    }
}

// ---------------------------------------------------------------------------
// Fix kernel: t_j = sum_cb tpart[batch][cb][j] (fp32, fixed order);
// b_j = (nu_j+1e-8)*ASCALE / t_j  (un-scales the x4096 on a).
// grid = 8*8 = 64 CTAs x 256 threads; thread owns one j.
// ---------------------------------------------------------------------------
__global__ void __launch_bounds__(256) fix_kernel(const float* __restrict__ nu) {
    int batch = blockIdx.x >> 3;
    int seg   = blockIdx.x & 7;
    int j     = seg * 256 + threadIdx.x;
    const __half* tp = g_tpart + (size_t)batch * CBS * PP + j;
    float acc[16];
#pragma unroll
    for (int m = 0; m < 16; m++) acc[m] = 0.f;
#pragma unroll 1
    for (int q = 0; q < 16; q++) {
#pragma unroll
        for (int m = 0; m < 16; m++)
            acc[m] += __half2float(tp[(size_t)(q * 16 + m) * PP]);
    }
    float tj = 0.f;
#pragma unroll
    for (int m = 0; m < 16; m++) tj += acc[m];
    int jj = batch * PP + j;
    float b = (nu[jj] + LOGEPS) * ASCALE / tj;
    g_b[jj]   = b;
    g_b_h[jj] = __float2half(b);
}

// ---------------------------------------------------------------------------
// Epilogue: pi = a_i * b_j * exp(-C/eps) from exact f32 C; copy C; cost partials.
// ---------------------------------------------------------------------------
__global__ void __launch_bounds__(256) epilogue_kernel(const float* __restrict__ C,
                                                       float* __restrict__ pi_out,
                                                       float* __restrict__ c_out) {
    int batch = blockIdx.x >> 9;
    int rb    = blockIdx.x & 511;
    int r0    = rb * 4;
    int t = threadIdx.x;
    int w = t >> 5, l = t & 31;

    const float* arow = g_a + batch * PP + r0;
    const float* bptr = g_b + batch * PP;
    float cost = 0.f;
#pragma unroll
    for (int q = 0; q < 8; q++) {
        int f  = t + q * 256;
        int rl = f >> 9;
        int c4 = f & 511;
        size_t idx = ((size_t)(batch * PP + r0 + rl)) * PP + (size_t)c4 * 4;
        float4 cv = *(const float4*)(C + idx);
        float  a  = arow[rl];
        float4 bv = *(const float4*)(bptr + c4 * 4);
        float4 pv;
        pv.x = a * bv.x * __expf(-INV_EPS * cv.x);
        pv.y = a * bv.y * __expf(-INV_EPS * cv.y);
        pv.z = a * bv.z * __expf(-INV_EPS * cv.z);
        pv.w = a * bv.w * __expf(-INV_EPS * cv.w);
        if (pi_out) *(float4*)(pi_out + idx) = pv;
        if (c_out)  *(float4*)(c_out + idx)  = cv;
        cost += pv.x * cv.x + pv.y * cv.y + pv.z * cv.z + pv.w * cv.w;
    }
#pragma unroll
    for (int off = 16; off; off >>= 1) cost += __shfl_xor_sync(0xffffffffu, cost, off);
    __shared__ float sm[8];
    if (l == 0) sm[w] = cost;
    __syncthreads();
    if (t == 0) {
        float sv = 0.f;
#pragma unroll
        for (int i = 0; i < 8; i++) sv += sm[i];
        g_part[blockIdx.x] = sv;
    }
}

// Final fixed-order cost reduction.
__global__ void cost_final_kernel(float* __restrict__ cost_out) {
    int w = threadIdx.x >> 5, l = threadIdx.x & 31;
    float s = 0.f;
#pragma unroll
    for (int m = 0; m < 16; m++) s += g_part[w * 512 + l + m * 32];
#pragma unroll
    for (int off = 16; off; off >>= 1) s += __shfl_xor_sync(0xffffffffu, s, off);
    if (l == 0) cost_out[w] = s;
}

// ---------------------------------------------------------------------------
#define ITER_SMEM (TILE_BYTES + 4096 + 32 + 32)   // 36928 B

extern "C" void kernel_launch(void* const* d_in, const int* in_sizes, int n_in,
                              void* d_out, int out_size) {
    const float* C  = (const float*)d_in[0];
    const float* mu = (const float*)d_in[1];
    const float* nu = (const float*)d_in[2];
    float* out = (float*)d_out;

    static bool attr_set = false;
    if (!attr_set) {
        cudaFuncSetAttribute(iter_kernel, cudaFuncAttributeMaxDynamicSharedMemorySize, ITER_SMEM);
        attr_set = true;
    }

    const long long M  = (long long)M_ELEMS;
    const long long os = (long long)out_size;
    float *cost = nullptr, *pi = nullptr, *cc = nullptr;
    if (os >= 8 + 2 * M)      { cost = out; pi = out + 8; cc = out + 8 + M; }
    else if (os == 2 * M)     { pi = out; cc = out + M; }
    else if (os == M + 8)     { cost = out; pi = out + 8; }
    else if (os == M)         { pi = out; }
    else if (os == 8)         { cost = out; }
    else                      { cost = out; if (os > 8 + M) { pi = out + 8; cc = out + 8 + M; }
                                else if (os > 8) pi = out + 8; }

    prologue_kernel<<<16384, 256>>>(C);
    for (int k = 0; k < NITER; k++) {
        iter_kernel<<<2048, 256, ITER_SMEM>>>(mu);
        fix_kernel<<<64, 256>>>(nu);
    }
    epilogue_kernel<<<4096, 256>>>(C, pi, cc);
    if (cost) cost_final_kernel<<<1, 256>>>(cost);
}

// round 13
// speedup vs baseline: 1.2590x; 1.2590x over previous
#include <cuda_runtime.h>
#include <cuda_fp16.h>
#include <cstdint>

// Sinkhorn (eps=0.1, 50 iters) on N=8, P1=P2=2048.
// Exp-domain matrix scaling, fp16 K = exp(-C/eps) (67 MB, L2-resident).
//   a = (mu+1e-8)/(K b);  b = (nu+1e-8)/(K^T a)
// R12: iter kernel unchanged from R8 (8-row tiles, half2 datapath, 68% occ).
// fix kernel rebuilt: 128 CTAs, uint4 fp16 loads (16/thread, MLP 16),
// smem fixed-order reduction. Removes the R8 regression (~10us -> ~2us).

#define NB 8
#define PP 2048
#define M_ELEMS (NB * (size_t)PP * (size_t)PP)   // 33,554,432
#define INV_EPS 10.0f
#define NITER 50
#define LOGEPS 1e-8f
#define ROWS_PER_CTA 8
#define CBS 256                                   // tiles (partial slices) per batch
#define TILE_BYTES (ROWS_PER_CTA * PP * 2)        // 32768
#define ASCALE 4096.0f

__device__ __half g_K[M_ELEMS];                   // 64 MiB
__device__ float  g_a[NB * PP];
__device__ float  g_b[NB * PP];
__device__ __half g_b_h[NB * PP];
__device__ __half g_tpart[NB * CBS * PP];         // 8 MiB fp16 partials (scaled x4096)
__device__ float  g_part[4096];

// ---------------- small PTX helpers ----------------
__device__ __forceinline__ uint32_t smem_u32(const void* p) {
    uint32_t a;
    asm("{ .reg .u64 t; cvta.to.shared.u64 t, %1; cvt.u32.u64 %0, t; }" : "=r"(a) : "l"(p));
    return a;
}
__device__ __forceinline__ void mbar_init(uint32_t mbar, uint32_t cnt) {
    asm volatile("mbarrier.init.shared.b64 [%0], %1;" :: "r"(mbar), "r"(cnt) : "memory");
}
__device__ __forceinline__ void mbar_expect_tx(uint32_t mbar, uint32_t bytes) {
    asm volatile("mbarrier.arrive.expect_tx.shared.b64 _, [%0], %1;" :: "r"(mbar), "r"(bytes) : "memory");
}
__device__ __forceinline__ void bulk_g2s(uint32_t dst, const void* src, uint32_t bytes, uint32_t mbar) {
    asm volatile("cp.async.bulk.shared::cta.global.mbarrier::complete_tx::bytes [%0], [%1], %2, [%3];"
                 :: "r"(dst), "l"(src), "r"(bytes), "r"(mbar) : "memory");
}
__device__ __forceinline__ void mbar_wait(uint32_t mbar, uint32_t parity) {
    uint32_t done;
    asm volatile("{\n\t.reg .pred p;\n\t"
                 "mbarrier.try_wait.parity.acquire.cta.shared::cta.b64 p, [%1], %2;\n\t"
                 "selp.b32 %0, 1, 0, p;\n\t}"
                 : "=r"(done) : "r"(mbar), "r"(parity) : "memory");
    if (!done) {
        asm volatile("{\n\t.reg .pred P1;\n\t"
                     "WL_%=:\n\t"
                     "mbarrier.try_wait.parity.acquire.cta.shared::cta.b64 P1, [%0], %1, 0x989680;\n\t"
                     "@P1 bra.uni WD_%=;\n\t"
                     "bra.uni WL_%=;\n\t"
                     "WD_%=:\n\t}"
                     :: "r"(mbar), "r"(parity) : "memory");
    }
}

// ---------------------------------------------------------------------------
// Prologue: K = fp16(exp(-C/eps)); init b = 1 (float and half).
// ---------------------------------------------------------------------------
__global__ void __launch_bounds__(256) prologue_kernel(const float* __restrict__ C) {
    size_t tid  = (size_t)blockIdx.x * 256 + threadIdx.x;
    size_t base = tid * 8;
    float4 c0 = *(const float4*)(C + base);
    float4 c1 = *(const float4*)(C + base + 4);
    union { __half2 h2[4]; uint4 u; } pk;
    pk.h2[0] = __floats2half2_rn(__expf(-INV_EPS * c0.x), __expf(-INV_EPS * c0.y));
    pk.h2[1] = __floats2half2_rn(__expf(-INV_EPS * c0.z), __expf(-INV_EPS * c0.w));
    pk.h2[2] = __floats2half2_rn(__expf(-INV_EPS * c1.x), __expf(-INV_EPS * c1.y));
    pk.h2[3] = __floats2half2_rn(__expf(-INV_EPS * c1.z), __expf(-INV_EPS * c1.w));
    *(uint4*)(g_K + base) = pk.u;
    if (tid < (size_t)NB * PP) {
        g_b[tid]   = 1.0f;
        g_b_h[tid] = __float2half(1.0f);
    }
}

// ---------------------------------------------------------------------------
// Fused iteration kernel (unchanged from R8). grid = 2048 x 256.
// ---------------------------------------------------------------------------
__global__ void __launch_bounds__(256) iter_kernel(const float* __restrict__ mu) {
    extern __shared__ char smem_raw[];
    __half*   Kt    = (__half*)smem_raw;                        // 32768 B
    __half*   b_sm  = (__half*)(smem_raw + TILE_BYTES);         // 4096 B
    __half2*  a_sm  = (__half2*)(smem_raw + TILE_BYTES + 4096); // 8 half2
    uint64_t* mbar_p = (uint64_t*)(smem_raw + TILE_BYTES + 4096 + 32);

    int batch = blockIdx.x >> 8;
    int cb    = blockIdx.x & 255;
    int row0  = cb * ROWS_PER_CTA;
    int t = threadIdx.x;
    int w = t >> 5, l = t & 31;

    uint32_t mbar0 = smem_u32(mbar_p);
    uint32_t ktad  = smem_u32(Kt);

    if (t == 0) { mbar_init(mbar0, 1); mbar_init(mbar0 + 8, 1); }
    __syncthreads();
    if (t == 0) {
        asm volatile("fence.proxy.async.shared::cta;" ::: "memory");
        const __half* src = g_K + ((size_t)(batch * PP + row0)) * PP;
        mbar_expect_tx(mbar0, TILE_BYTES / 2);
        bulk_g2s(ktad, src, TILE_BYTES / 2, mbar0);
        mbar_expect_tx(mbar0 + 8, TILE_BYTES / 2);
        bulk_g2s(ktad + TILE_BYTES / 2, src + PP * (ROWS_PER_CTA / 2), TILE_BYTES / 2, mbar0 + 8);
    }

    // Cooperative load of b (fp16) into smem.
    {
        const __half* bp = g_b_h + batch * PP + t * 8;
        *(uint4*)(b_sm + t * 8) = *(const uint4*)bp;
    }
    __syncthreads();

    // Warps 0-3 consume rows 0-3 (chunk 0), warps 4-7 rows 4-7 (chunk 1).
    mbar_wait(mbar0 + (w >= 4 ? 8 : 0), 0);

    // ---- Phase A: warp w sums row w ----
    {
        const __half* Krow = Kt + w * PP;
        float ax = 0.f, ay = 0.f;
#pragma unroll
        for (int it = 0; it < 8; it++) {
            int off = (it * 32 + l) * 8;
            uint4 kv = *(const uint4*)(Krow + off);
            uint4 bv = *(const uint4*)(b_sm + off);
            const __half2* kh = (const __half2*)&kv;
            const __half2* bh = (const __half2*)&bv;
            __half2 p0 = __hmul2(kh[0], bh[0]);
            __half2 p1 = __hmul2(kh[1], bh[1]);
            __half2 p2 = __hmul2(kh[2], bh[2]);
            __half2 p3 = __hmul2(kh[3], bh[3]);
            __half2 s2 = __hadd2(__hadd2(p0, p1), __hadd2(p2, p3));
            float2 f = __half22float2(s2);
            ax += f.x; ay += f.y;
        }
        float s = ax + ay;
#pragma unroll
        for (int off = 16; off; off >>= 1) s += __shfl_xor_sync(0xffffffffu, s, off);
        if (l == 0) {
            int row = batch * PP + row0 + w;
            float av = (mu[row] + LOGEPS) / s;
            g_a[row] = av;
            a_sm[w]  = __float2half2_rn(av * ASCALE);
        }
    }
    __syncthreads();

    // ---- Phase B: thread t owns cols 8t..8t+7; HFMA2 accum over 8 rows ----
    {
        __half2 acc0 = __float2half2_rn(0.f);
        __half2 acc1 = acc0, acc2 = acc0, acc3 = acc0;
#pragma unroll
        for (int r = 0; r < ROWS_PER_CTA; r++) {
            uint4 kv = *(const uint4*)(Kt + r * PP + t * 8);
            __half2 a2 = a_sm[r];
            const __half2* kh = (const __half2*)&kv;
            acc0 = __hfma2(kh[0], a2, acc0);
            acc1 = __hfma2(kh[1], a2, acc1);
            acc2 = __hfma2(kh[2], a2, acc2);
            acc3 = __hfma2(kh[3], a2, acc3);
        }
        union { __half2 h2[4]; uint4 u; } st;
        st.h2[0] = acc0; st.h2[1] = acc1; st.h2[2] = acc2; st.h2[3] = acc3;
        *(uint4*)(g_tpart + ((size_t)(batch * CBS + cb)) * PP + t * 8) = st.u;
    }
}

// ---------------------------------------------------------------------------
// Fix kernel v2: t_j = sum_cb tpart[batch][cb][j];  b_j = (nu_j+1e-8)*ASCALE/t_j.
// grid = 8*16 = 128 CTAs x 256 threads. CTA owns 128 j.
// Thread t: sg = t>>4 (slice-group of 16 slices), jo = t&15 (j-octet).
// 16 x uint4 fp16 loads per thread (coalesced, MLP 16) -> f32 partials ->
// 8 KB smem fixed-order reduction over 16 slice-groups.
// ---------------------------------------------------------------------------
__global__ void __launch_bounds__(256) fix_kernel(const float* __restrict__ nu) {
    __shared__ float red[16][128];   // [slice-group][j-local]
    int batch = blockIdx.x >> 4;
    int cbid  = blockIdx.x & 15;
    int jbase = cbid * 128;
    int t  = threadIdx.x;
    int sg = t >> 4;
    int jo = t & 15;

    const __half* base = g_tpart + (size_t)batch * CBS * PP
                       + (size_t)(sg * 16) * PP + jbase + jo * 8;
    float acc[8];
#pragma unroll
    for (int c = 0; c < 8; c++) acc[c] = 0.f;
#pragma unroll
    for (int q = 0; q < 16; q++) {
        uint4 v = *(const uint4*)(base + (size_t)q * PP);
        const __half2* h = (const __half2*)&v;
#pragma unroll
        for (int c = 0; c < 4; c++) {
            float2 f = __half22float2(h[c]);
            acc[2 * c + 0] += f.x;
            acc[2 * c + 1] += f.y;
        }
    }
#pragma unroll
    for (int c = 0; c < 8; c++) red[sg][jo * 8 + c] = acc[c];
    __syncthreads();

    if (t < 128) {
        float tj = 0.f;
#pragma unroll
        for (int s = 0; s < 16; s++) tj += red[s][t];
        int jj = batch * PP + jbase + t;
        float b = (nu[jj] + LOGEPS) * ASCALE / tj;
        g_b[jj]   = b;
        g_b_h[jj] = __float2half(b);
    }
}

// ---------------------------------------------------------------------------
// Epilogue: pi = a_i * b_j * exp(-C/eps) from exact f32 C; copy C; cost partials.
// ---------------------------------------------------------------------------
__global__ void __launch_bounds__(256) epilogue_kernel(const float* __restrict__ C,
                                                       float* __restrict__ pi_out,
                                                       float* __restrict__ c_out) {
    int batch = blockIdx.x >> 9;
    int rb    = blockIdx.x & 511;
    int r0    = rb * 4;
    int t = threadIdx.x;
    int w = t >> 5, l = t & 31;

    const float* arow = g_a + batch * PP + r0;
    const float* bptr = g_b + batch * PP;
    float cost = 0.f;
#pragma unroll
    for (int q = 0; q < 8; q++) {
        int f  = t + q * 256;
        int rl = f >> 9;
        int c4 = f & 511;
        size_t idx = ((size_t)(batch * PP + r0 + rl)) * PP + (size_t)c4 * 4;
        float4 cv = *(const float4*)(C + idx);
        float  a  = arow[rl];
        float4 bv = *(const float4*)(bptr + c4 * 4);
        float4 pv;
        pv.x = a * bv.x * __expf(-INV_EPS * cv.x);
        pv.y = a * bv.y * __expf(-INV_EPS * cv.y);
        pv.z = a * bv.z * __expf(-INV_EPS * cv.z);
        pv.w = a * bv.w * __expf(-INV_EPS * cv.w);
        if (pi_out) *(float4*)(pi_out + idx) = pv;
        if (c_out)  *(float4*)(c_out + idx)  = cv;
        cost += pv.x * cv.x + pv.y * cv.y + pv.z * cv.z + pv.w * cv.w;
    }
#pragma unroll
    for (int off = 16; off; off >>= 1) cost += __shfl_xor_sync(0xffffffffu, cost, off);
    __shared__ float sm[8];
    if (l == 0) sm[w] = cost;
    __syncthreads();
    if (t == 0) {
        float sv = 0.f;
#pragma unroll
        for (int i = 0; i < 8; i++) sv += sm[i];
        g_part[blockIdx.x] = sv;
    }
}

// Final fixed-order cost reduction.
__global__ void cost_final_kernel(float* __restrict__ cost_out) {
    int w = threadIdx.x >> 5, l = threadIdx.x & 31;
    float s = 0.f;
#pragma unroll
    for (int m = 0; m < 16; m++) s += g_part[w * 512 + l + m * 32];
#pragma unroll
    for (int off = 16; off; off >>= 1) s += __shfl_xor_sync(0xffffffffu, s, off);
    if (l == 0) cost_out[w] = s;
}

// ---------------------------------------------------------------------------
#define ITER_SMEM (TILE_BYTES + 4096 + 32 + 32)   // 36928 B

extern "C" void kernel_launch(void* const* d_in, const int* in_sizes, int n_in,
                              void* d_out, int out_size) {
    const float* C  = (const float*)d_in[0];
    const float* mu = (const float*)d_in[1];
    const float* nu = (const float*)d_in[2];
    float* out = (float*)d_out;

    static bool attr_set = false;
    if (!attr_set) {
        cudaFuncSetAttribute(iter_kernel, cudaFuncAttributeMaxDynamicSharedMemorySize, ITER_SMEM);
        attr_set = true;
    }

    const long long M  = (long long)M_ELEMS;
    const long long os = (long long)out_size;
    float *cost = nullptr, *pi = nullptr, *cc = nullptr;
    if (os >= 8 + 2 * M)      { cost = out; pi = out + 8; cc = out + 8 + M; }
    else if (os == 2 * M)     { pi = out; cc = out + M; }
    else if (os == M + 8)     { cost = out; pi = out + 8; }
    else if (os == M)         { pi = out; }
    else if (os == 8)         { cost = out; }
    else                      { cost = out; if (os > 8 + M) { pi = out + 8; cc = out + 8 + M; }
                                else if (os > 8) pi = out + 8; }

    prologue_kernel<<<16384, 256>>>(C);
    for (int k = 0; k < NITER; k++) {
        iter_kernel<<<2048, 256, ITER_SMEM>>>(mu);
        fix_kernel<<<128, 256>>>(nu);
    }
    epilogue_kernel<<<4096, 256>>>(C, pi, cc);
    if (cost) cost_final_kernel<<<1, 256>>>(cost);
}